// round 2
// baseline (speedup 1.0000x reference)
#include <cuda_runtime.h>
#include <cuda_bf16.h>
#include <cstdint>

// Problem constants
#define Bn   96
#define Cn   128
#define Hn   64
#define Wn   128
#define TSn  16
#define FUSn 32

#define Z_OFF  0
#define HC_OFF 786432
#define R_OFF  1572864

// -------- device scratch (no allocs allowed) --------
__device__ int   g_argmax[Bn];
__device__ float g_gap[Bn * Cn];
__device__ float g_wd[Bn * Cn * 9];

// ============================================================
// Kernel 1: per-batch argmax over H_piece (8192 elems), first-max tiebreak
// ============================================================
__global__ void __launch_bounds__(256) argmax_kernel(const float* __restrict__ hp) {
    __shared__ float sv[256];
    __shared__ int   si[256];
    int b = blockIdx.x;
    int tid = threadIdx.x;
    const float* p = hp + b * (Hn * Wn);
    float best = -1e30f; int bi = 0x7fffffff;
    for (int i = tid; i < Hn * Wn; i += 256) {
        float v = p[i];
        if (v > best) { best = v; bi = i; }   // ascending => keeps first occurrence
    }
    sv[tid] = best; si[tid] = bi;
    __syncthreads();
    for (int s = 128; s > 0; s >>= 1) {
        if (tid < s) {
            float ov = sv[tid + s]; int oi = si[tid + s];
            if (ov > sv[tid] || (ov == sv[tid] && oi < si[tid])) { sv[tid] = ov; si[tid] = oi; }
        }
        __syncthreads();
    }
    if (tid == 0) g_argmax[b] = si[0];
}

// ============================================================
// Kernel 2: bilinear template extract (writes R) + GAP
// grid = 96 blocks, 128 threads (one per channel)
// ============================================================
__global__ void __launch_bounds__(128) extract_kernel(const float* __restrict__ Hf,
                                                      float* __restrict__ Rout) {
    __shared__ int   sx0[TSn], sx1[TSn], sy0[TSn], sy1[TSn];
    __shared__ float swx[TSn], swy[TSn];
    int b = blockIdx.x;
    int tid = threadIdx.x;

    if (tid < 32) {
        int am = g_argmax[b];
        if (tid < 16) {
            int j = tid;
            float u = (float)(am % Wn);
            float fx = (-7.5f + (float)j) + u * ((float)Wn / (float)(Wn - 1)) - 0.5f;
            fx = fminf(fmaxf(fx, 0.0f), (float)(Wn - 1));
            float x0 = floorf(fx);
            int x0i = (int)x0; if (x0i < 0) x0i = 0; if (x0i > Wn - 1) x0i = Wn - 1;
            int x1i = x0i + 1; if (x1i > Wn - 1) x1i = Wn - 1;
            sx0[j] = x0i; sx1[j] = x1i; swx[j] = fx - x0;
        } else {
            int i = tid - 16;
            float v = (float)(am / Wn);
            float fy = (-7.5f + (float)i) + v * ((float)Hn / (float)(Hn - 1)) - 0.5f;
            fy = fminf(fmaxf(fy, 0.0f), (float)(Hn - 1));
            float y0 = floorf(fy);
            int y0i = (int)y0; if (y0i < 0) y0i = 0; if (y0i > Hn - 1) y0i = Hn - 1;
            int y1i = y0i + 1; if (y1i > Hn - 1) y1i = Hn - 1;
            sy0[i] = y0i; sy1[i] = y1i; swy[i] = fy - y0;
        }
    }
    __syncthreads();

    int c = tid;
    const float* img = Hf + ((size_t)(b * Cn + c)) * (Hn * Wn);
    float* rbase = Rout + ((size_t)(b * Cn + c)) * (TSn * TSn);
    float sum = 0.0f;
    for (int i = 0; i < TSn; ++i) {
        const float* r0 = img + sy0[i] * Wn;
        const float* r1 = img + sy1[i] * Wn;
        float wy = swy[i];
        #pragma unroll 4
        for (int j = 0; j < TSn; ++j) {
            int x0 = sx0[j], x1 = sx1[j];
            float wx = swx[j];
            float v00 = r0[x0], v01 = r0[x1], v10 = r1[x0], v11 = r1[x1];
            float val = v00 * (1.0f - wx) * (1.0f - wy)
                      + v01 * wx * (1.0f - wy)
                      + v10 * (1.0f - wx) * wy
                      + v11 * wx * wy;
            rbase[i * TSn + j] = val;
            sum += val;
        }
    }
    g_gap[b * Cn + c] = sum * (1.0f / 256.0f);
}

// ============================================================
// Kernel 3: fc1(relu) -> fc2 -> per-channel 3x3 L2-normalize
// grid = 96 blocks, 576 threads (18 warps); warp-per-output GEMV
// ============================================================
__global__ void __launch_bounds__(576) fc_kernel(const float* __restrict__ fc1w,
                                                 const float* __restrict__ fc1b,
                                                 const float* __restrict__ fc2w,
                                                 const float* __restrict__ fc2b) {
    __shared__ float s_gap[128];
    __shared__ float s_hdn[576];
    __shared__ float s_kp[1152];
    int b = blockIdx.x;
    int tid = threadIdx.x;
    int warp = tid >> 5, lane = tid & 31;

    if (tid < 128) s_gap[tid] = g_gap[b * 128 + tid];
    __syncthreads();

    // fc1: 576 outputs, dot over 128
    for (int o = warp; o < 576; o += 18) {
        const float* wrow = fc1w + (size_t)o * 128;
        float p = 0.0f;
        #pragma unroll
        for (int j = 0; j < 4; ++j) {
            int h = lane + 32 * j;
            p = fmaf(s_gap[h], wrow[h], p);
        }
        #pragma unroll
        for (int off = 16; off > 0; off >>= 1) p += __shfl_xor_sync(0xffffffffu, p, off);
        if (lane == 0) s_hdn[o] = fmaxf(p + fc1b[o], 0.0f);
    }
    __syncthreads();

    // fc2: 1152 outputs, dot over 576
    for (int o = warp; o < 1152; o += 18) {
        const float* wrow = fc2w + (size_t)o * 576;
        float p = 0.0f;
        #pragma unroll
        for (int j = 0; j < 18; ++j) {
            int h = lane + 32 * j;
            p = fmaf(s_hdn[h], wrow[h], p);
        }
        #pragma unroll
        for (int off = 16; off > 0; off >>= 1) p += __shfl_xor_sync(0xffffffffu, p, off);
        if (lane == 0) s_kp[o] = p + fc2b[o];
    }
    __syncthreads();

    // normalize per (c): 9 taps
    if (tid < 128) {
        int c = tid;
        float v[9]; float nrm = 0.0f;
        #pragma unroll
        for (int k = 0; k < 9; ++k) { v[k] = s_kp[c * 9 + k]; nrm = fmaf(v[k], v[k], nrm); }
        nrm = sqrtf(nrm);
        float inv = 1.0f / fmaxf(nrm, 1e-12f);
        #pragma unroll
        for (int k = 0; k < 9; ++k) g_wd[b * 1152 + c * 9 + k] = v[k] * inv;
    }
}

// ============================================================
// Kernel 4: per-batch 128-ch 3x3 correlation + sigmoid  (the big one)
// tile 128(W) x 32(Y) per block, 512 threads, 8-px vertical strips,
// triple-buffered cp.async over channels (1 barrier per channel).
// smem: 3 * 34*136 floats + 1152 weight floats = 60096 B (dynamic)
// ============================================================
#define BUF_ROWS   34
#define BUF_STRIDE 136
#define BUF_FLOATS (BUF_ROWS * BUF_STRIDE)   // 4624
#define WS_OFF     (3 * BUF_FLOATS)          // 13872
#define CORR_SMEM  ((WS_OFF + 1152) * 4)     // 60096 bytes

__device__ __forceinline__ void cp16(float* dst, const float* src) {
    unsigned sa = (unsigned)__cvta_generic_to_shared(dst);
    asm volatile("cp.async.cg.shared.global [%0], [%1], 16;\n" :: "r"(sa), "l"(src));
}

__device__ __forceinline__ void corr_issue(float* bufs, const float* Hb,
                                           int c, int slot, int ybase, int tid) {
    const float* src = Hb + (size_t)c * (Hn * Wn);
    float* dstbase = bufs + slot * BUF_FLOATS;
    for (int idx = tid; idx < BUF_ROWS * 32; idx += 512) {
        int r = idx >> 5, g = idx & 31;
        int yimg = ybase - 1 + r;
        if ((unsigned)yimg < (unsigned)Hn) {
            cp16(dstbase + r * BUF_STRIDE + 4 + g * 4, src + yimg * Wn + g * 4);
        }
    }
    asm volatile("cp.async.commit_group;\n");
}

__global__ void __launch_bounds__(512) corr_kernel(const float* __restrict__ Hf,
                                                   float* __restrict__ hc) {
    extern __shared__ float dsm[];
    float* bufs = dsm;
    float* ws   = dsm + WS_OFF;

    int b = blockIdx.y;
    int ybase = blockIdx.x * 32;
    int tid = threadIdx.x;
    int x = tid & 127;
    int ys = tid >> 7;   // 0..3

    for (int i = tid; i < WS_OFF; i += 512) bufs[i] = 0.0f;
    for (int i = tid; i < 1152; i += 512) ws[i] = g_wd[b * 1152 + i];
    __syncthreads();

    const float* Hb = Hf + (size_t)b * (Cn * Hn * Wn);

    corr_issue(bufs, Hb, 0, 0, ybase, tid);
    corr_issue(bufs, Hb, 1, 1, ybase, tid);

    float acc[8];
    #pragma unroll
    for (int k = 0; k < 8; ++k) acc[k] = 0.0f;

    for (int c = 0; c < Cn; ++c) {
        if (c < Cn - 1) { asm volatile("cp.async.wait_group 1;\n" ::: "memory"); }
        else            { asm volatile("cp.async.wait_group 0;\n" ::: "memory"); }
        __syncthreads();
        if (c + 2 < Cn) corr_issue(bufs, Hb, c + 2, (c + 2) % 3, ybase, tid);

        const float* W9 = ws + c * 9;
        float w0 = W9[0], w1 = W9[1], w2 = W9[2];
        float w3 = W9[3], w4 = W9[4], w5 = W9[5];
        float w6 = W9[6], w7 = W9[7], w8 = W9[8];

        const float* S = bufs + (c % 3) * BUF_FLOATS + (ys * 8) * BUF_STRIDE + 4 + x;
        #pragma unroll
        for (int r = 0; r < 10; ++r) {
            float a = S[r * BUF_STRIDE - 1];
            float m = S[r * BUF_STRIDE];
            float d = S[r * BUF_STRIDE + 1];
            if (r <= 7)           acc[r]     = fmaf(a, w0, fmaf(m, w1, fmaf(d, w2, acc[r])));
            if (r >= 1 && r <= 8) acc[r - 1] = fmaf(a, w3, fmaf(m, w4, fmaf(d, w5, acc[r - 1])));
            if (r >= 2)           acc[r - 2] = fmaf(a, w6, fmaf(m, w7, fmaf(d, w8, acc[r - 2])));
        }
    }

    int y0 = ybase + ys * 8;
    #pragma unroll
    for (int k = 0; k < 8; ++k) {
        float o = 1.0f / (1.0f + __expf(-acc[k]));
        hc[b * (Hn * Wn) + (y0 + k) * Wn + x] = o;
    }
}

// ============================================================
// Kernel 5: conv1(2->32,3x3)+BN(folded)+swish+conv2(1x1)+sigmoid
// packed f32x2 FMAs over channel pairs. tile 128x16, 256 threads.
// ============================================================
typedef unsigned long long ull;

__device__ __forceinline__ ull pk2(float lo, float hi) {
    ull r; asm("mov.b64 %0, {%1,%2};" : "=l"(r) : "f"(lo), "f"(hi)); return r;
}
__device__ __forceinline__ void upk2(ull v, float& lo, float& hi) {
    asm("mov.b64 {%0,%1}, %2;" : "=f"(lo), "=f"(hi) : "l"(v));
}
__device__ __forceinline__ ull fma2(ull a, ull b, ull c) {
    ull d; asm("fma.rn.f32x2 %0, %1, %2, %3;" : "=l"(d) : "l"(a), "l"(b), "l"(c)); return d;
}
__device__ __forceinline__ float swishf(float y) {
    return y * __frcp_rn(1.0f + __expf(-y));
}

#define FT_ROWS   18
#define FT_STRIDE 136
#define FT_FLOATS (FT_ROWS * FT_STRIDE)  // 2448

__global__ void __launch_bounds__(256) fuse_kernel(const float* __restrict__ Hg,
                                                   const float* __restrict__ hc,
                                                   const float* __restrict__ c1w,
                                                   const float* __restrict__ c1b,
                                                   const float* __restrict__ bng,
                                                   const float* __restrict__ bnb,
                                                   const float* __restrict__ bnm,
                                                   const float* __restrict__ bnv,
                                                   const float* __restrict__ c2w,
                                                   const float* __restrict__ c2b,
                                                   float* __restrict__ zout) {
    __shared__ float tg[FT_FLOATS];
    __shared__ float tc[FT_FLOATS];
    __shared__ ull   w2s[288];     // [t(18)][p(16)]
    __shared__ ull   bias2[16];
    __shared__ float sb[32], bb[32], c2s[32];
    __shared__ float sb2;

    int b = blockIdx.y;
    int ybase = blockIdx.x * 16;
    int tid = threadIdx.x;

    if (tid < 32) {
        int f = tid;
        float s = bng[f] * rsqrtf(bnv[f] + 1e-5f);
        sb[f] = s;
        bb[f] = (c1b[f] - bnm[f]) * s + bnb[f];
        c2s[f] = c2w[f];
    }
    if (tid == 0) sb2 = c2b[0];
    for (int i = tid; i < FT_FLOATS; i += 256) { tg[i] = 0.0f; tc[i] = 0.0f; }
    __syncthreads();

    // BUGFIX (R1): 288 entries but only 256 threads — must stride.
    for (int i = tid; i < 288; i += 256) {
        int t = i >> 4, p = i & 15;
        w2s[i] = pk2(c1w[(2 * p) * 18 + t] * sb[2 * p],
                     c1w[(2 * p + 1) * 18 + t] * sb[2 * p + 1]);
    }
    if (tid < 16) bias2[tid] = pk2(bb[2 * tid], bb[2 * tid + 1]);

    for (int idx = tid; idx < FT_ROWS * Wn; idx += 256) {
        int r = idx >> 7, xx = idx & 127;
        int yimg = ybase - 1 + r;
        if ((unsigned)yimg < (unsigned)Hn) {
            int goff = b * (Hn * Wn) + yimg * Wn + xx;
            tg[r * FT_STRIDE + 4 + xx] = Hg[goff];
            tc[r * FT_STRIDE + 4 + xx] = hc[goff];
        }
    }
    __syncthreads();

    int x = tid & 127;
    int ys = tid >> 7;
    int y0 = ybase + ys * 8;

    for (int k = 0; k < 8; ++k) {
        ull acc[16];
        #pragma unroll
        for (int p = 0; p < 16; ++p) acc[p] = bias2[p];

        float xin[18];
        #pragma unroll
        for (int r = 0; r < 3; ++r) {
            int row = (ys * 8 + k + r) * FT_STRIDE + 4 + x;
            xin[r * 3 + 0] = tg[row - 1];
            xin[r * 3 + 1] = tg[row];
            xin[r * 3 + 2] = tg[row + 1];
            xin[9 + r * 3 + 0] = tc[row - 1];
            xin[9 + r * 3 + 1] = tc[row];
            xin[9 + r * 3 + 2] = tc[row + 1];
        }

        #pragma unroll
        for (int t = 0; t < 18; ++t) {
            ull v2 = pk2(xin[t], xin[t]);
            #pragma unroll
            for (int p = 0; p < 16; ++p) acc[p] = fma2(v2, w2s[t * 16 + p], acc[p]);
        }

        float z = 0.0f;
        #pragma unroll
        for (int p = 0; p < 16; ++p) {
            float lo, hi; upk2(acc[p], lo, hi);
            z = fmaf(c2s[2 * p], swishf(lo), z);
            z = fmaf(c2s[2 * p + 1], swishf(hi), z);
        }
        float out = 1.0f / (1.0f + __expf(-(z + sb2)));
        zout[b * (Hn * Wn) + (y0 + k) * Wn + x] = out;
    }
}

// ============================================================
extern "C" void kernel_launch(void* const* d_in, const int* in_sizes, int n_in,
                              void* d_out, int out_size) {
    const float* Hf   = (const float*)d_in[0];
    const float* hp   = (const float*)d_in[1];
    const float* Hg   = (const float*)d_in[2];
    const float* fc1w = (const float*)d_in[3];
    const float* fc1b = (const float*)d_in[4];
    const float* fc2w = (const float*)d_in[5];
    const float* fc2b = (const float*)d_in[6];
    const float* c1w  = (const float*)d_in[7];
    const float* c1b  = (const float*)d_in[8];
    const float* bng  = (const float*)d_in[9];
    const float* bnb  = (const float*)d_in[10];
    const float* bnm  = (const float*)d_in[11];
    const float* bnv  = (const float*)d_in[12];
    const float* c2w  = (const float*)d_in[13];
    const float* c2b  = (const float*)d_in[14];

    float* out = (float*)d_out;
    float* z  = out + Z_OFF;
    float* hc = out + HC_OFF;
    float* R  = out + R_OFF;

    argmax_kernel<<<Bn, 256>>>(hp);
    extract_kernel<<<Bn, 128>>>(Hf, R);
    fc_kernel<<<Bn, 576>>>(fc1w, fc1b, fc2w, fc2b);

    cudaFuncSetAttribute(corr_kernel, cudaFuncAttributeMaxDynamicSharedMemorySize, CORR_SMEM);
    corr_kernel<<<dim3(2, Bn), 512, CORR_SMEM>>>(Hf, hc);

    fuse_kernel<<<dim3(4, Bn), 256>>>(Hg, hc, c1w, c1b, bng, bnb, bnm, bnv, c2w, c2b, z);
}